// round 1
// baseline (speedup 1.0000x reference)
#include <cuda_runtime.h>
#include <cuda_bf16.h>

// Heat-equation stencil: 400 sequential steps of
//   u <- mask * (u + 0.225 * lap5(u) + 1e-7 * a)
// on a 1501x1501 fp32 grid, Dirichlet (zero) boundaries.
//
// Baseline: one kernel per step, ping-pong between two __device__ scratch
// buffers. Entire working set (~27 MB) lives in L2.

#define H_GRID 1501
#define NPTS (H_GRID * H_GRID)
#define NUM_T 400
#define STEP_PARAM 0.225f
#define DELTA_T 1e-7f

// Scratch ping-pong buffers (allocation-free rule: __device__ globals).
__device__ float g_bufA[NPTS];
__device__ float g_bufB[NPTS];

__global__ __launch_bounds__(256)
void furnace_step_kernel(const float* __restrict__ src,
                         float* __restrict__ dst,
                         const float* __restrict__ a)
{
    int j = blockIdx.x * blockDim.x + threadIdx.x;  // column (contiguous)
    int i = blockIdx.y;                             // row
    if (j >= H_GRID) return;

    int idx = i * H_GRID + j;

    if (i == 0 || i == H_GRID - 1 || j == 0 || j == H_GRID - 1) {
        dst[idx] = 0.0f;   // Dirichlet mask
        return;
    }

    float c  = src[idx];
    float up = src[idx - H_GRID];
    float dn = src[idx + H_GRID];
    float lf = src[idx - 1];
    float rt = src[idx + 1];

    float lap = (up + dn) + (lf + rt) - 4.0f * c;
    dst[idx] = c + STEP_PARAM * lap + DELTA_T * a[idx];
}

extern "C" void kernel_launch(void* const* d_in, const int* in_sizes, int n_in,
                              void* d_out, int out_size)
{
    const float* u0 = (const float*)d_in[0];
    const float* a  = (const float*)d_in[1];
    float* out = (float*)d_out;

    float* bufA = nullptr;
    float* bufB = nullptr;
    cudaGetSymbolAddress((void**)&bufA, g_bufA);
    cudaGetSymbolAddress((void**)&bufB, g_bufB);

    dim3 block(256, 1);
    dim3 grid((H_GRID + 255) / 256, H_GRID);

    for (int t = 0; t < NUM_T; t++) {
        const float* src;
        float* dst;
        if (t == 0)            src = u0;
        else                   src = (t % 2 == 1) ? bufA : bufB;
        if (t == NUM_T - 1)    dst = out;
        else                   dst = (t % 2 == 0) ? bufA : bufB;

        furnace_step_kernel<<<grid, block>>>(src, dst, a);
    }
}

// round 2
// speedup vs baseline: 2.4249x; 2.4249x over previous
#include <cuda_runtime.h>
#include <cuda_bf16.h>

// Temporal-blocked heat stencil: T=8 steps fused per kernel launch.
// u <- mask * (u + 0.225*lap5(u) + 1e-7*a), 400 total steps, 1501x1501 fp32.
//
// Tile geometry: smem tile 128(x) x 48(y), halo 8, output 112x32 per block.
// Ring-r cells go stale after step r (trapezoid); output region = rings >= 8.
// Data in padded (stride-1576) __device__ ping-pong buffers for aligned float4.

#define HN 1501
#define PW 1576          // padded row stride (multiple of 4, covers halo reads)
#define PH 1512          // padded height (covers halo reads)
#define PW4 (PW / 4)

#define SW 128           // smem tile width (floats)
#define SH 48            // smem tile height
#define HALO 8
#define TSTEPS 8
#define TX 112           // output cols per tile
#define TY 32            // output rows per tile
#define NBX 14           // ceil(1501/112)
#define NBY 47           // ceil(1501/32)
#define NLAUNCH 50       // 400 / 8

#define STEP_PARAM 0.225f
#define DELTA_T 1e-7f

// Padded ping-pong + forcing buffers (zero-initialized; padding stays 0
// because every store into padding is mask*...=0 or never happens).
__device__ float4 g_U0[PW4 * PH];
__device__ float4 g_U1[PW4 * PH];
__device__ float4 g_A [PW4 * PH];

__global__ __launch_bounds__(256)
void stencil8_kernel(const float* __restrict__ srcP,
                     float* __restrict__ dstP,
                     const float* __restrict__ aP)
{
    __shared__ float4 sU[2][SH][SW / 4];   // 48 KB

    const int tid  = threadIdx.x;
    const int tx4  = tid & 31;        // float4 column 0..31
    const int band = tid >> 5;        // 0..7, 6 rows each
    const int y0   = band * 6;

    const int gx0 = blockIdx.x * TX - HALO;
    const int gy0 = blockIdx.y * TY - HALO;
    const int gx  = gx0 + tx4 * 4;

    // ---- load u tile + a tile (a stays in registers) ----
    float4 aReg[6];
    const float4 Z = make_float4(0.f, 0.f, 0.f, 0.f);
#pragma unroll
    for (int r = 0; r < 6; r++) {
        int y  = y0 + r;
        int gy = gy0 + y;
        bool inb = (gx >= 0) && (gy >= 0);   // high side covered by padding
        float4 v = Z, av = Z;
        if (inb) {
            v  = *reinterpret_cast<const float4*>(srcP + gy * PW + gx);
            av = *reinterpret_cast<const float4*>(aP   + gy * PW + gx);
        }
        sU[0][y][tx4] = v;
        aReg[r] = av;
    }

    // Dirichlet mask per x-component (domain boundary + outside -> 0)
    float4 mx;
    mx.x = (gx + 0 >= 1 && gx + 0 <= HN - 2) ? 1.f : 0.f;
    mx.y = (gx + 1 >= 1 && gx + 1 <= HN - 2) ? 1.f : 0.f;
    mx.z = (gx + 2 >= 1 && gx + 2 <= HN - 2) ? 1.f : 0.f;
    mx.w = (gx + 3 >= 1 && gx + 3 <= HN - 2) ? 1.f : 0.f;

    const int lidx = (tx4 == 0)  ? 0        : tx4 * 4 - 1;
    const int ridx = (tx4 == 31) ? SW - 1   : tx4 * 4 + 4;

    __syncthreads();

    // ---- 8 fused timesteps, smem ping-pong ----
#pragma unroll 1
    for (int s = 0; s < TSTEPS; s++) {
        const int sb = s & 1, db = sb ^ 1;

        float4 up = sU[sb][(y0 > 0) ? y0 - 1 : 0][tx4];
        float4 cu = sU[sb][y0][tx4];

#pragma unroll
        for (int r = 0; r < 6; r++) {
            int y = y0 + r;
            float4 dn = sU[sb][(y < SH - 1) ? y + 1 : SH - 1][tx4];

            if (y >= 1 && y <= SH - 2) {
                const float* rowF = reinterpret_cast<const float*>(&sU[sb][y][0]);
                float lf = rowF[lidx];
                float rt = rowF[ridx];

                int   gy = gy0 + y;
                float my = (gy >= 1 && gy <= HN - 2) ? 1.f : 0.f;

                float4 lap;
                lap.x = (up.x + dn.x) + (lf   + cu.y) - 4.f * cu.x;
                lap.y = (up.y + dn.y) + (cu.x + cu.z) - 4.f * cu.y;
                lap.z = (up.z + dn.z) + (cu.y + cu.w) - 4.f * cu.z;
                lap.w = (up.w + dn.w) + (cu.z + rt  ) - 4.f * cu.w;

                float4 o;
                o.x = (mx.x * my) * fmaf(STEP_PARAM, lap.x, fmaf(DELTA_T, aReg[r].x, cu.x));
                o.y = (mx.y * my) * fmaf(STEP_PARAM, lap.y, fmaf(DELTA_T, aReg[r].y, cu.y));
                o.z = (mx.z * my) * fmaf(STEP_PARAM, lap.z, fmaf(DELTA_T, aReg[r].z, cu.z));
                o.w = (mx.w * my) * fmaf(STEP_PARAM, lap.w, fmaf(DELTA_T, aReg[r].w, cu.w));

                sU[db][y][tx4] = o;
            }
            up = cu; cu = dn;
        }
        __syncthreads();
    }

    // ---- store output region (rings >= HALO); final state in sU[0] ----
    if (tx4 >= 2 && tx4 < 30) {
#pragma unroll
        for (int r = 0; r < 6; r++) {
            int y = y0 + r;
            if (y >= HALO && y < HALO + TY) {
                int gy = gy0 + y;
                *reinterpret_cast<float4*>(dstP + gy * PW + gx) = sU[0][y][tx4];
            }
        }
    }
}

__global__ __launch_bounds__(256)
void copy_in_kernel(const float* __restrict__ u0, const float* __restrict__ a)
{
    int j = blockIdx.x * blockDim.x + threadIdx.x;
    int i = blockIdx.y;
    if (j >= HN) return;
    float* U = reinterpret_cast<float*>(g_U0);
    float* A = reinterpret_cast<float*>(g_A);
    U[i * PW + j] = u0[i * HN + j];
    A[i * PW + j] = a [i * HN + j];
}

__global__ __launch_bounds__(256)
void copy_out_kernel(float* __restrict__ out)
{
    int j = blockIdx.x * blockDim.x + threadIdx.x;
    int i = blockIdx.y;
    if (j >= HN) return;
    const float* U = reinterpret_cast<const float*>(g_U0);
    out[i * HN + j] = U[i * PW + j];
}

extern "C" void kernel_launch(void* const* d_in, const int* in_sizes, int n_in,
                              void* d_out, int out_size)
{
    const float* u0 = (const float*)d_in[0];
    const float* a  = (const float*)d_in[1];
    float* out = (float*)d_out;

    float *U0, *U1, *A;
    cudaGetSymbolAddress((void**)&U0, g_U0);
    cudaGetSymbolAddress((void**)&U1, g_U1);
    cudaGetSymbolAddress((void**)&A,  g_A);

    dim3 cgrid((HN + 255) / 256, HN);
    copy_in_kernel<<<cgrid, 256>>>(u0, a);

    dim3 sgrid(NBX, NBY);
    for (int l = 0; l < NLAUNCH; l++) {
        const float* src = (l & 1) ? U1 : U0;
        float*       dst = (l & 1) ? U0 : U1;
        stencil8_kernel<<<sgrid, 256>>>(src, dst, A);
    }
    // NLAUNCH even -> final state back in g_U0

    copy_out_kernel<<<cgrid, 256>>>(out);
}

// round 3
// speedup vs baseline: 3.4384x; 1.4179x over previous
#include <cuda_runtime.h>
#include <cuda_bf16.h>

// Temporal-blocked heat stencil, register/shuffle edition. T=8 steps/launch.
// u <- mask * (u + 0.225*lap5(u) + 1e-7*a), 400 steps, 1501x1501 fp32.
//
// Tile 128(x) x 48(y), halo 8, output 112x32. Warp = band of 6 rows x 128 cols
// (each lane owns a float4 column group). u and dt*a live in registers;
// x-neighbors via shuffles; y band-boundary rows exchanged through 16KB smem.

#define HN 1501
#define PW 1576
#define PH 1512
#define PW4 (PW / 4)

#define SW 128
#define SH 48
#define HALO 8
#define TSTEPS 8
#define TX 112
#define TY 32
#define NBX 14
#define NBY 47
#define NLAUNCH 50

#define STEP_PARAM 0.225f
#define DELTA_T 1e-7f

__device__ float4 g_U0[PW4 * PH];
__device__ float4 g_U1[PW4 * PH];
__device__ float4 g_A [PW4 * PH];

__global__ __launch_bounds__(256)
void stencil8_kernel(const float* __restrict__ srcP,
                     float* __restrict__ dstP,
                     const float* __restrict__ aP)
{
    // Band-boundary exchange rows, double-buffered by step parity: 16 KB.
    __shared__ float4 sE[2][8][2][32];

    const int tid  = threadIdx.x;
    const int lane = tid & 31;
    const int band = tid >> 5;          // 0..7
    const int y0   = band * 6;

    const int gx0 = blockIdx.x * TX - HALO;
    const int gy0 = blockIdx.y * TY - HALO;
    const int gx  = gx0 + lane * 4;

    const bool edgeBlock = (blockIdx.x == 0) || (blockIdx.x == NBX - 1) ||
                           (blockIdx.y == 0) || (blockIdx.y == NBY - 1);

    // ---- load u rows + pre-scaled forcing into registers ----
    float4 u[6], aS[6];
    const float4 Z = make_float4(0.f, 0.f, 0.f, 0.f);
#pragma unroll
    for (int r = 0; r < 6; r++) {
        int gy = gy0 + y0 + r;
        bool inb = (gx >= 0) && (gy >= 0);      // high side covered by padding
        float4 v = Z, av = Z;
        if (inb) {
            v  = *reinterpret_cast<const float4*>(srcP + gy * PW + gx);
            av = *reinterpret_cast<const float4*>(aP   + gy * PW + gx);
        }
        u[r] = v;
        aS[r].x = DELTA_T * av.x; aS[r].y = DELTA_T * av.y;
        aS[r].z = DELTA_T * av.z; aS[r].w = DELTA_T * av.w;
    }

    // Dirichlet masks (only used on edge blocks)
    float4 mx;
    mx.x = (gx + 0 >= 1 && gx + 0 <= HN - 2) ? 1.f : 0.f;
    mx.y = (gx + 1 >= 1 && gx + 1 <= HN - 2) ? 1.f : 0.f;
    mx.z = (gx + 2 >= 1 && gx + 2 <= HN - 2) ? 1.f : 0.f;
    mx.w = (gx + 3 >= 1 && gx + 3 <= HN - 2) ? 1.f : 0.f;
    float my[6];
#pragma unroll
    for (int r = 0; r < 6; r++) {
        int gy = gy0 + y0 + r;
        my[r] = (gy >= 1 && gy <= HN - 2) ? 1.f : 0.f;
    }

    // ---- 8 fused timesteps ----
#pragma unroll 1
    for (int s = 0; s < TSTEPS; s++) {
        const int p = s & 1;

        // publish band boundary rows (start-of-step values)
        sE[p][band][0][lane] = u[0];
        sE[p][band][1][lane] = u[5];
        __syncthreads();

        float4 up4 = (band > 0) ? sE[p][band - 1][1][lane] : u[0];
        float4 dn4 = (band < 7) ? sE[p][band + 1][0][lane] : u[5];

        float4 prevOld = up4;
#pragma unroll
        for (int r = 0; r < 6; r++) {
            float4 cu = u[r];
            float4 nx = (r < 5) ? u[r + 1] : dn4;

            float lf = __shfl_up_sync(0xffffffffu, cu.w, 1);
            float rt = __shfl_down_sync(0xffffffffu, cu.x, 1);

            float4 sm;
            sm.x = (prevOld.x + nx.x) + (lf   + cu.y);
            sm.y = (prevOld.y + nx.y) + (cu.x + cu.z);
            sm.z = (prevOld.z + nx.z) + (cu.y + cu.w);
            sm.w = (prevOld.w + nx.w) + (cu.z + rt);

            float4 un;
            un.x = fmaf(STEP_PARAM, sm.x, fmaf(0.1f, cu.x, aS[r].x));
            un.y = fmaf(STEP_PARAM, sm.y, fmaf(0.1f, cu.y, aS[r].y));
            un.z = fmaf(STEP_PARAM, sm.z, fmaf(0.1f, cu.z, aS[r].z));
            un.w = fmaf(STEP_PARAM, sm.w, fmaf(0.1f, cu.w, aS[r].w));

            if (edgeBlock) {
                float m = my[r];
                un.x *= mx.x * m; un.y *= mx.y * m;
                un.z *= mx.z * m; un.w *= mx.w * m;
            }

            prevOld = cu;
            u[r] = un;
        }
        __syncthreads();   // keep step segments separated (reads of sE[p] done)
    }

    // ---- store output region: rows 8..39 of tile, cols 8..119 ----
    if (lane >= 2 && lane < 30) {
#pragma unroll
        for (int r = 0; r < 6; r++) {
            int y = y0 + r;
            if (y >= HALO && y < HALO + TY) {
                int gy = gy0 + y;
                *reinterpret_cast<float4*>(dstP + gy * PW + gx) = u[r];
            }
        }
    }
}

__global__ __launch_bounds__(256)
void copy_in_kernel(const float* __restrict__ u0, const float* __restrict__ a)
{
    int j = blockIdx.x * blockDim.x + threadIdx.x;
    int i = blockIdx.y;
    if (j >= HN) return;
    float* U = reinterpret_cast<float*>(g_U0);
    float* A = reinterpret_cast<float*>(g_A);
    U[i * PW + j] = u0[i * HN + j];
    A[i * PW + j] = a [i * HN + j];
}

__global__ __launch_bounds__(256)
void copy_out_kernel(float* __restrict__ out)
{
    int j = blockIdx.x * blockDim.x + threadIdx.x;
    int i = blockIdx.y;
    if (j >= HN) return;
    const float* U = reinterpret_cast<const float*>(g_U0);
    out[i * HN + j] = U[i * PW + j];
}

extern "C" void kernel_launch(void* const* d_in, const int* in_sizes, int n_in,
                              void* d_out, int out_size)
{
    const float* u0 = (const float*)d_in[0];
    const float* a  = (const float*)d_in[1];
    float* out = (float*)d_out;

    float *U0, *U1, *A;
    cudaGetSymbolAddress((void**)&U0, g_U0);
    cudaGetSymbolAddress((void**)&U1, g_U1);
    cudaGetSymbolAddress((void**)&A,  g_A);

    dim3 cgrid((HN + 255) / 256, HN);
    copy_in_kernel<<<cgrid, 256>>>(u0, a);

    dim3 sgrid(NBX, NBY);
    for (int l = 0; l < NLAUNCH; l++) {
        const float* src = (l & 1) ? U1 : U0;
        float*       dst = (l & 1) ? U0 : U1;
        stencil8_kernel<<<sgrid, 256>>>(src, dst, A);
    }
    // NLAUNCH even -> final state back in g_U0

    copy_out_kernel<<<cgrid, 256>>>(out);
}

// round 4
// speedup vs baseline: 4.1400x; 1.2041x over previous
#include <cuda_runtime.h>
#include <cuda_bf16.h>

// Temporal-blocked heat stencil, packed-f32x2 register/shuffle edition.
// T=8 steps/launch, tile 128x48, halo 8, output 112x32, grid 14x47, 50 launches.
// Lane state: interleaved pairs A=(c0,c2), B=(c1,c3) as 64-bit f32x2 regs.

#define HN 1501
#define PW 1576
#define PH 1512
#define PW4 (PW / 4)

#define HALO 8
#define TSTEPS 8
#define TX 112
#define TY 32
#define NBX 14
#define NBY 47
#define NLAUNCH 50

#define STEP_PARAM 0.225f
#define DELTA_T 1e-7f

typedef unsigned long long u64;

__device__ float4 g_U0[PW4 * PH];
__device__ float4 g_U1[PW4 * PH];
__device__ float4 g_A [PW4 * PH];

__device__ __forceinline__ u64 pk2(float lo, float hi) {
    u64 r; asm("mov.b64 %0, {%1, %2};" : "=l"(r) : "f"(lo), "f"(hi)); return r;
}
__device__ __forceinline__ void upk2(u64 v, float& lo, float& hi) {
    asm("mov.b64 {%0, %1}, %2;" : "=f"(lo), "=f"(hi) : "l"(v));
}
__device__ __forceinline__ u64 add2(u64 a, u64 b) {
    u64 r; asm("add.rn.f32x2 %0, %1, %2;" : "=l"(r) : "l"(a), "l"(b)); return r;
}
__device__ __forceinline__ u64 mul2(u64 a, u64 b) {
    u64 r; asm("mul.rn.f32x2 %0, %1, %2;" : "=l"(r) : "l"(a), "l"(b)); return r;
}
__device__ __forceinline__ u64 fma2(u64 a, u64 b, u64 c) {
    u64 r; asm("fma.rn.f32x2 %0, %1, %2, %3;" : "=l"(r) : "l"(a), "l"(b), "l"(c)); return r;
}

__global__ __launch_bounds__(256)
void stencil8_kernel(const float* __restrict__ srcP,
                     float* __restrict__ dstP,
                     const float* __restrict__ aP)
{
    __shared__ ulonglong2 sE[2][8][2][32];   // parity-double-buffered exchange rows

    const int tid  = threadIdx.x;
    const int lane = tid & 31;
    const int band = tid >> 5;
    const int y0   = band * 6;

    const int gx0 = blockIdx.x * TX - HALO;
    const int gy0 = blockIdx.y * TY - HALO;
    const int gx  = gx0 + lane * 4;

    const bool edgeBlock = (blockIdx.x == 0) || (blockIdx.x == NBX - 1) ||
                           (blockIdx.y == 0) || (blockIdx.y == NBY - 1);

    // ---- load u + pre-scaled forcing, interleave into (c0,c2)/(c1,c3) pairs ----
    u64 uA[6], uB[6], aA[6], aB[6];
    const float4 Z = make_float4(0.f, 0.f, 0.f, 0.f);
#pragma unroll
    for (int r = 0; r < 6; r++) {
        int gy = gy0 + y0 + r;
        bool inb = (gx >= 0) && (gy >= 0);
        float4 v = Z, av = Z;
        if (inb) {
            v  = *reinterpret_cast<const float4*>(srcP + gy * PW + gx);
            av = *reinterpret_cast<const float4*>(aP   + gy * PW + gx);
        }
        uA[r] = pk2(v.x, v.z);
        uB[r] = pk2(v.y, v.w);
        aA[r] = pk2(DELTA_T * av.x, DELTA_T * av.z);
        aB[r] = pk2(DELTA_T * av.y, DELTA_T * av.w);
    }

    // Dirichlet masks (edge blocks only)
    const u64 mA = pk2((gx + 0 >= 1 && gx + 0 <= HN - 2) ? 1.f : 0.f,
                       (gx + 2 >= 1 && gx + 2 <= HN - 2) ? 1.f : 0.f);
    const u64 mB = pk2((gx + 1 >= 1 && gx + 1 <= HN - 2) ? 1.f : 0.f,
                       (gx + 3 >= 1 && gx + 3 <= HN - 2) ? 1.f : 0.f);
    float my[6];
#pragma unroll
    for (int r = 0; r < 6; r++) {
        int gy = gy0 + y0 + r;
        my[r] = (gy >= 1 && gy <= HN - 2) ? 1.f : 0.f;
    }

    const u64 K225 = pk2(STEP_PARAM, STEP_PARAM);
    const u64 K01  = pk2(0.1f, 0.1f);

    // ---- 8 fused timesteps, single barrier per step ----
#pragma unroll 1
    for (int s = 0; s < TSTEPS; s++) {
        const int p = s & 1;

        sE[p][band][0][lane] = make_ulonglong2(uA[0], uB[0]);
        sE[p][band][1][lane] = make_ulonglong2(uA[5], uB[5]);
        __syncthreads();

        ulonglong2 upP = (band > 0) ? sE[p][band - 1][1][lane]
                                    : make_ulonglong2(uA[0], uB[0]);
        ulonglong2 dnP = (band < 7) ? sE[p][band + 1][0][lane]
                                    : make_ulonglong2(uA[5], uB[5]);

        u64 prevA = upP.x, prevB = upP.y;
#pragma unroll
        for (int r = 0; r < 6; r++) {
            u64 A = uA[r], B = uB[r];
            u64 nxA = (r < 5) ? uA[r + 1] : dnP.x;
            u64 nxB = (r < 5) ? uB[r + 1] : dnP.y;

            float c0, c2, c1, c3;
            upk2(A, c0, c2);
            upk2(B, c1, c3);

            float lf = __shfl_up_sync(0xffffffffu, c3, 1);
            float rt = __shfl_down_sync(0xffffffffu, c0, 1);

            u64 VA = add2(prevA, nxA);
            u64 VB = add2(prevB, nxB);
            u64 HA = add2(pk2(lf, c1), B);      // (lf+c1, c1+c3)
            u64 HB = add2(A, pk2(c2, rt));      // (c0+c2, c2+rt)

            u64 smA = add2(VA, HA);
            u64 smB = add2(VB, HB);

            u64 unA = fma2(K225, smA, fma2(K01, A, aA[r]));
            u64 unB = fma2(K225, smB, fma2(K01, B, aB[r]));

            if (edgeBlock) {
                u64 mr = pk2(my[r], my[r]);
                unA = mul2(mul2(unA, mA), mr);
                unB = mul2(mul2(unB, mB), mr);
            }

            prevA = A; prevB = B;
            uA[r] = unA; uB[r] = unB;
        }
        // no trailing barrier: parity buffers + next step's barrier order
        // step-s readers of sE[p] before step-(s+2) writers of sE[p].
    }

    // ---- store output region (rows 8..39, cols 8..119), de-interleave ----
    if (lane >= 2 && lane < 30) {
#pragma unroll
        for (int r = 0; r < 6; r++) {
            int y = y0 + r;
            if (y >= HALO && y < HALO + TY) {
                int gy = gy0 + y;
                float o0, o1, o2, o3;
                upk2(uA[r], o0, o2);
                upk2(uB[r], o1, o3);
                *reinterpret_cast<float4*>(dstP + gy * PW + gx) =
                    make_float4(o0, o1, o2, o3);
            }
        }
    }
}

__global__ __launch_bounds__(256)
void copy_in_kernel(const float* __restrict__ u0, const float* __restrict__ a)
{
    int j = blockIdx.x * blockDim.x + threadIdx.x;
    int i = blockIdx.y;
    if (j >= HN) return;
    float* U = reinterpret_cast<float*>(g_U0);
    float* A = reinterpret_cast<float*>(g_A);
    U[i * PW + j] = u0[i * HN + j];
    A[i * PW + j] = a [i * HN + j];
}

__global__ __launch_bounds__(256)
void copy_out_kernel(float* __restrict__ out)
{
    int j = blockIdx.x * blockDim.x + threadIdx.x;
    int i = blockIdx.y;
    if (j >= HN) return;
    const float* U = reinterpret_cast<const float*>(g_U0);
    out[i * HN + j] = U[i * PW + j];
}

extern "C" void kernel_launch(void* const* d_in, const int* in_sizes, int n_in,
                              void* d_out, int out_size)
{
    const float* u0 = (const float*)d_in[0];
    const float* a  = (const float*)d_in[1];
    float* out = (float*)d_out;

    float *U0, *U1, *A;
    cudaGetSymbolAddress((void**)&U0, g_U0);
    cudaGetSymbolAddress((void**)&U1, g_U1);
    cudaGetSymbolAddress((void**)&A,  g_A);

    dim3 cgrid((HN + 255) / 256, HN);
    copy_in_kernel<<<cgrid, 256>>>(u0, a);

    dim3 sgrid(NBX, NBY);
    for (int l = 0; l < NLAUNCH; l++) {
        const float* src = (l & 1) ? U1 : U0;
        float*       dst = (l & 1) ? U0 : U1;
        stencil8_kernel<<<sgrid, 256>>>(src, dst, A);
    }

    copy_out_kernel<<<cgrid, 256>>>(out);
}